// round 15
// baseline (speedup 1.0000x reference)
#include <cuda_runtime.h>
#include <cuda_bf16.h>
#include <cuda_fp16.h>

// Problem constants (fixed by the dataset):
//   acts: (B, T, U+1, V) fp32, labels: (B, U) int32, act_lens/label_lens: (B,) int32
#define BB  16
#define TT  200
#define UU  100
#define VV  256
#define UP1 101          // U + 1
#define NEG_INF (-1e30f)
#define LOG2E 1.4426950408889634f
#define LN2   0.6931471805599453f

// Diagonal-major operand tensors (log2 domain), written by the softmax kernel:
//   BD[b][d][u] (fp32) = blank[t][u] * LOG2E at d = t+u
//   ED[b][d][u] (fp16) = emit [t][u-1] * LOG2E at d = t+u   (col 0 unused)
// Rows padded to 312 (loop prefetch reads up to row ~304); pitch 104.
#define DROWS  312
#define DPITCH 104
#define DSTR   26        // row stride in float4 / uint2 units (104/4)

// Scratch (no cudaMalloc allowed). Unwritten cells hold zeros/stale data;
// they can never influence valid lattice cells (deps flow up in u, fwd in t)
// and all arithmetic on them stays finite (no inf/NaN).
__device__ float    g_blankD[BB * DROWS * DPITCH];   // 2.08 MB
__device__ __half   g_emitD [BB * DROWS * DPITCH];   // 1.04 MB
__device__ float    g_perb  [BB];                    // per-example nll / label_len
__device__ unsigned g_done = 0;                      // block-completion counter

// ---------------------------------------------------------------------------
// Kernel 1: fused log-softmax gather, TWO (b,t,u) nodes per warp (MLP=4).
// Skips nodes outside the live lattice region. Stores DIAGONAL-MAJOR in the
// log2 domain (the scatter is free: lane-0 stores were already scattered).
// ---------------------------------------------------------------------------
__global__ __launch_bounds__(256) void rnnt_softmax_kernel(
    const float* __restrict__ acts,
    const int*   __restrict__ labels,
    const int*   __restrict__ act_lens,
    const int*   __restrict__ label_lens)
{
    const int P = BB * TT * UP1;                       // 323200 (even)
    int w    = blockIdx.x * 8 + (threadIdx.x >> 5);    // warp id
    int lane = threadIdx.x & 31;
    int n0   = w * 2;
    if (n0 >= P) return;
    int n1 = n0 + 1;

    int u0 = n0 % UP1, bt0 = n0 / UP1, t0 = bt0 % TT, b0i = bt0 / TT;
    int u1 = n1 % UP1, bt1 = n1 / UP1, t1 = bt1 % TT, b1i = bt1 / TT;

    bool L0 = (t0 < __ldg(act_lens + b0i)) && (u0 <= __ldg(label_lens + b0i));
    bool L1 = (t1 < __ldg(act_lens + b1i)) && (u1 <= __ldg(label_lens + b1i));
    if (!L0 && !L1) return;

    const float4* p0 = reinterpret_cast<const float4*>(acts) + (size_t)n0 * (VV / 4);
    const float4* p1 = p0 + (VV / 4);

    float4 a0 = {0,0,0,0}, c0 = {0,0,0,0}, a1 = {0,0,0,0}, c1 = {0,0,0,0};
    if (L0) { a0 = p0[lane]; c0 = p0[lane + 32]; }
    if (L1) { a1 = p1[lane]; c1 = p1[lane + 32]; }

    float m0 = fmaxf(fmaxf(fmaxf(a0.x, a0.y), fmaxf(a0.z, a0.w)),
                     fmaxf(fmaxf(c0.x, c0.y), fmaxf(c0.z, c0.w)));
    float m1 = fmaxf(fmaxf(fmaxf(a1.x, a1.y), fmaxf(a1.z, a1.w)),
                     fmaxf(fmaxf(c1.x, c1.y), fmaxf(c1.z, c1.w)));
    #pragma unroll
    for (int o = 16; o; o >>= 1) {
        m0 = fmaxf(m0, __shfl_xor_sync(0xffffffffu, m0, o));
        m1 = fmaxf(m1, __shfl_xor_sync(0xffffffffu, m1, o));
    }

    float s0 = __expf(a0.x - m0) + __expf(a0.y - m0) + __expf(a0.z - m0) + __expf(a0.w - m0)
             + __expf(c0.x - m0) + __expf(c0.y - m0) + __expf(c0.z - m0) + __expf(c0.w - m0);
    float s1 = __expf(a1.x - m1) + __expf(a1.y - m1) + __expf(a1.z - m1) + __expf(a1.w - m1)
             + __expf(c1.x - m1) + __expf(c1.y - m1) + __expf(c1.z - m1) + __expf(c1.w - m1);
    #pragma unroll
    for (int o = 16; o; o >>= 1) {
        s0 += __shfl_xor_sync(0xffffffffu, s0, o);
        s1 += __shfl_xor_sync(0xffffffffu, s1, o);
    }

    if (lane == 0) {
        if (L0) {
            float logZ = m0 + __logf(s0);
            size_t base = (size_t)b0i * DROWS * DPITCH;
            g_blankD[base + (size_t)(t0 + u0) * DPITCH + u0] = (a0.x - logZ) * LOG2E;
            if (u0 < UU) {
                int lbl  = labels[b0i * UU + u0];
                float lv = __ldg(acts + (size_t)n0 * VV + lbl);
                g_emitD[base + (size_t)(t0 + u0 + 1) * DPITCH + (u0 + 1)] =
                    __float2half((lv - logZ) * LOG2E);
            }
        }
        if (L1) {
            float logZ = m1 + __logf(s1);
            size_t base = (size_t)b1i * DROWS * DPITCH;
            g_blankD[base + (size_t)(t1 + u1) * DPITCH + u1] = (a1.x - logZ) * LOG2E;
            if (u1 < UU) {
                int lbl  = labels[b1i * UU + u1];
                float lv = __ldg(acts + (size_t)n1 * VV + lbl);
                g_emitD[base + (size_t)(t1 + u1 + 1) * DPITCH + (u1 + 1)] =
                    __float2half((lv - logZ) * LOG2E);
            }
        }
    }
}

// log-sum-exp of two values in the log2 domain.
__device__ __forceinline__ float la2(float x, float y)
{
    float mx = fmaxf(x, y);
    float mn = fminf(x, y);
    return mx + __log2f(1.0f + exp2f(mn - mx));
}

// ---------------------------------------------------------------------------
// Kernel 2: per-example forward DP, ONE warp per example, lane l owns the
// contiguous u-block {4l..4l+3}. Per diagonal: one coalesced LDG.128 (blank
// row d-1) + one LDG.64 (emit row d, fp16) from the diagonal-major tensors,
// one shfl_up for the block-boundary neighbor, four logaddexp cells whose
// left deps (k=1..3) are the lane's own OLD registers. 4-deep software
// pipeline hides the L2 latency. No smem, no barriers. Runs a fixed
// round-up-to-4 diagonal count; the terminal alpha is snapshot at d == dmax.
// Mean-reduction fused via completion counter.
// ---------------------------------------------------------------------------
__global__ __launch_bounds__(32) void rnnt_dp_kernel(
    const int* __restrict__ act_lens,
    const int* __restrict__ label_lens,
    float*     __restrict__ out)
{
    int b  = blockIdx.x;
    int Tl = act_lens[b];
    int Ul = label_lens[b];
    int l  = threadIdx.x;
    const unsigned F = 0xffffffffu;

    const float4* bdp = reinterpret_cast<const float4*>(
                            g_blankD + (size_t)b * DROWS * DPITCH) + l;
    const uint2*  edp = reinterpret_cast<const uint2*>(
                            g_emitD  + (size_t)b * DROWS * DPITCH) + l;

    int  dmax = (Tl - 1) + Ul;                 // last diagonal (>= 149)
    int  kf   = Ul & 3;
    bool amI  = (l == (Ul >> 2));

    float a0 = (l == 0) ? 0.0f : NEG_INF;      // alpha[0][4l+k], log2 domain
    float a1 = NEG_INF, a2 = NEG_INF, a3 = NEG_INF;
    float res = NEG_INF;

    // Prime the 4-deep pipeline: stages hold (blank row d-1, emit row d).
    float4 B0 = bdp[0 * DSTR], B1 = bdp[1 * DSTR],
           B2 = bdp[2 * DSTR], B3 = bdp[3 * DSTR];
    uint2  E0 = edp[1 * DSTR], E1 = edp[2 * DSTR],
           E2 = edp[3 * DSTR], E3 = edp[4 * DSTR];

#define STEP(Bv, Eu, dd)                                                      \
    do {                                                                      \
        float2 e01 = __half22float2(*reinterpret_cast<const __half2*>(&Eu.x));\
        float2 e23 = __half22float2(*reinterpret_cast<const __half2*>(&Eu.y));\
        float sh = __shfl_up_sync(F, a3, 1);                                  \
        if (l == 0) sh = NEG_INF;                                             \
        float n0 = la2(a0 + Bv.x, sh + e01.x);                                \
        float n1 = la2(a1 + Bv.y, a0 + e01.y);                                \
        float n2 = la2(a2 + Bv.z, a1 + e23.x);                                \
        float n3 = la2(a3 + Bv.w, a2 + e23.y);                                \
        a0 = n0; a1 = n1; a2 = n2; a3 = n3;                                   \
        if ((dd) == dmax && amI)                                              \
            res = (kf == 0) ? a0 : (kf == 1) ? a1 : (kf == 2) ? a2 : a3;      \
    } while (0)

    int dlim = ((dmax + 3) >> 2) << 2;         // <= 300
    for (int d0 = 1; d0 <= dlim; d0 += 4) {
        STEP(B0, E0, d0);
        B0 = bdp[(d0 + 3) * DSTR];  E0 = edp[(d0 + 4) * DSTR];
        STEP(B1, E1, d0 + 1);
        B1 = bdp[(d0 + 4) * DSTR];  E1 = edp[(d0 + 5) * DSTR];
        STEP(B2, E2, d0 + 2);
        B2 = bdp[(d0 + 5) * DSTR];  E2 = edp[(d0 + 6) * DSTR];
        STEP(B3, E3, d0 + 3);
        B3 = bdp[(d0 + 6) * DSTR];  E3 = edp[(d0 + 7) * DSTR];
    }
#undef STEP

    // Terminal: loss_b = -(alpha(Tl-1,Ul) + blank(Tl-1,Ul)) * ln2 / Ul.
    if (amI) {
        float bl = g_blankD[(size_t)b * DROWS * DPITCH
                            + (size_t)dmax * DPITCH + Ul];
        g_perb[b] = -((res + bl) * LN2) / (float)Ul;
        __threadfence();
        unsigned done = atomicAdd(&g_done, 1u);
        if (done == BB - 1) {                  // last example: fold the mean
            __threadfence();
            float s = 0.0f;
            #pragma unroll
            for (int i = 0; i < BB; ++i) s += __ldcg(&g_perb[i]);
            out[0] = s / (float)BB;
            g_done = 0;                        // reset for next graph replay
        }
    }
}

extern "C" void kernel_launch(void* const* d_in, const int* in_sizes, int n_in,
                              void* d_out, int out_size)
{
    const float* acts       = (const float*)d_in[0];
    const int*   labels     = (const int*)  d_in[1];
    const int*   act_lens   = (const int*)  d_in[2];
    const int*   label_lens = (const int*)  d_in[3];
    float*       out        = (float*)d_out;

    const int P     = BB * TT * UP1;          // lattice nodes
    const int pairs = P / 2;                  // two nodes per warp
    int blocks = (pairs + 7) / 8;             // 8 warps per 256-thread block
    rnnt_softmax_kernel<<<blocks, 256>>>(acts, labels, act_lens, label_lens);

    rnnt_dp_kernel<<<BB, 32>>>(act_lens, label_lens, out);
}

// round 16
// speedup vs baseline: 1.2039x; 1.2039x over previous
#include <cuda_runtime.h>
#include <cuda_bf16.h>
#include <cuda_fp16.h>

// Problem constants (fixed by the dataset):
//   acts: (B, T, U+1, V) fp32, labels: (B, U) int32, act_lens/label_lens: (B,) int32
#define BB  16
#define TT  200
#define UU  100
#define VV  256
#define UP1 101          // U + 1
#define NEG_INF (-1e30f)
#define LOG2E 1.4426950408889634f
#define LN2   0.6931471805599453f

// Diagonal-major operand tensors (log2 domain), written by the softmax kernel:
//   BD[b][d][u] (fp32) = blank[t][u] * LOG2E at d = t+u
//   ED[b][d][u] (fp16) = emit [t][u-1] * LOG2E at d = t+u   (col 0 unused)
#define DROWS  312       // global rows (padded)
#define DPITCH 104
#define DSTR   26        // row stride in float4 / uint2 units (104/4)
#define SROWS  302       // rows staged to smem (dmax <= 299; prefetch clamped)
#define SMEM_BYTES (SROWS * DPITCH * 4 + SROWS * DPITCH * 2)   // 188,448 B

// Scratch (no cudaMalloc allowed). Unwritten cells hold stale/garbage data;
// they can never influence valid lattice cells (deps flow up in u, fwd in t)
// and all arithmetic on them stays finite (no inf/NaN).
__device__ float    g_blankD[BB * DROWS * DPITCH];   // 2.08 MB
__device__ __half   g_emitD [BB * DROWS * DPITCH];   // 1.04 MB
__device__ float    g_perb  [BB];                    // per-example nll / label_len
__device__ unsigned g_done = 0;                      // block-completion counter

// ---------------------------------------------------------------------------
// Kernel 1: fused log-softmax gather, TWO (b,t,u) nodes per warp (MLP=4).
// Skips nodes outside the live lattice region. Stores DIAGONAL-MAJOR in the
// log2 domain (the scatter is free: lane-0 stores were already scattered).
// ---------------------------------------------------------------------------
__global__ __launch_bounds__(256) void rnnt_softmax_kernel(
    const float* __restrict__ acts,
    const int*   __restrict__ labels,
    const int*   __restrict__ act_lens,
    const int*   __restrict__ label_lens)
{
    const int P = BB * TT * UP1;                       // 323200 (even)
    int w    = blockIdx.x * 8 + (threadIdx.x >> 5);    // warp id
    int lane = threadIdx.x & 31;
    int n0   = w * 2;
    if (n0 >= P) return;
    int n1 = n0 + 1;

    int u0 = n0 % UP1, bt0 = n0 / UP1, t0 = bt0 % TT, b0i = bt0 / TT;
    int u1 = n1 % UP1, bt1 = n1 / UP1, t1 = bt1 % TT, b1i = bt1 / TT;

    bool L0 = (t0 < __ldg(act_lens + b0i)) && (u0 <= __ldg(label_lens + b0i));
    bool L1 = (t1 < __ldg(act_lens + b1i)) && (u1 <= __ldg(label_lens + b1i));
    if (!L0 && !L1) return;

    const float4* p0 = reinterpret_cast<const float4*>(acts) + (size_t)n0 * (VV / 4);
    const float4* p1 = p0 + (VV / 4);

    float4 a0 = {0,0,0,0}, c0 = {0,0,0,0}, a1 = {0,0,0,0}, c1 = {0,0,0,0};
    if (L0) { a0 = p0[lane]; c0 = p0[lane + 32]; }
    if (L1) { a1 = p1[lane]; c1 = p1[lane + 32]; }

    float m0 = fmaxf(fmaxf(fmaxf(a0.x, a0.y), fmaxf(a0.z, a0.w)),
                     fmaxf(fmaxf(c0.x, c0.y), fmaxf(c0.z, c0.w)));
    float m1 = fmaxf(fmaxf(fmaxf(a1.x, a1.y), fmaxf(a1.z, a1.w)),
                     fmaxf(fmaxf(c1.x, c1.y), fmaxf(c1.z, c1.w)));
    #pragma unroll
    for (int o = 16; o; o >>= 1) {
        m0 = fmaxf(m0, __shfl_xor_sync(0xffffffffu, m0, o));
        m1 = fmaxf(m1, __shfl_xor_sync(0xffffffffu, m1, o));
    }

    float s0 = __expf(a0.x - m0) + __expf(a0.y - m0) + __expf(a0.z - m0) + __expf(a0.w - m0)
             + __expf(c0.x - m0) + __expf(c0.y - m0) + __expf(c0.z - m0) + __expf(c0.w - m0);
    float s1 = __expf(a1.x - m1) + __expf(a1.y - m1) + __expf(a1.z - m1) + __expf(a1.w - m1)
             + __expf(c1.x - m1) + __expf(c1.y - m1) + __expf(c1.z - m1) + __expf(c1.w - m1);
    #pragma unroll
    for (int o = 16; o; o >>= 1) {
        s0 += __shfl_xor_sync(0xffffffffu, s0, o);
        s1 += __shfl_xor_sync(0xffffffffu, s1, o);
    }

    if (lane == 0) {
        if (L0) {
            float logZ = m0 + __logf(s0);
            size_t base = (size_t)b0i * DROWS * DPITCH;
            g_blankD[base + (size_t)(t0 + u0) * DPITCH + u0] = (a0.x - logZ) * LOG2E;
            if (u0 < UU) {
                int lbl  = labels[b0i * UU + u0];
                float lv = __ldg(acts + (size_t)n0 * VV + lbl);
                g_emitD[base + (size_t)(t0 + u0 + 1) * DPITCH + (u0 + 1)] =
                    __float2half((lv - logZ) * LOG2E);
            }
        }
        if (L1) {
            float logZ = m1 + __logf(s1);
            size_t base = (size_t)b1i * DROWS * DPITCH;
            g_blankD[base + (size_t)(t1 + u1) * DPITCH + u1] = (a1.x - logZ) * LOG2E;
            if (u1 < UU) {
                int lbl  = labels[b1i * UU + u1];
                float lv = __ldg(acts + (size_t)n1 * VV + lbl);
                g_emitD[base + (size_t)(t1 + u1 + 1) * DPITCH + (u1 + 1)] =
                    __float2half((lv - logZ) * LOG2E);
            }
        }
    }
}

// log-sum-exp of two values in the log2 domain.
__device__ __forceinline__ float la2(float x, float y)
{
    float mx = fmaxf(x, y);
    float mn = fminf(x, y);
    return mx + __log2f(1.0f + exp2f(mn - mx));
}

// ---------------------------------------------------------------------------
// Kernel 2: per-example forward DP, ONE warp computing, lane l owns the
// contiguous u-block {4l..4l+3}. Operands come from SMEM in the diagonal-
// major layout: per diagonal one conflict-free LDS.128 (blank row) + one
// LDS.64 (emit row, fp16), prefetched 4 stages ahead so the 29-cyc LDS
// latency is fully off the alpha chain. Four warps stage the 188 KB tiles
// (L2-resident, coalesced) then three exit. No barriers in the loop.
// Mean-reduction fused via completion counter.
// ---------------------------------------------------------------------------
__global__ __launch_bounds__(128) void rnnt_dp_kernel(
    const int* __restrict__ act_lens,
    const int* __restrict__ label_lens,
    float*     __restrict__ out)
{
    int b   = blockIdx.x;
    int Tl  = act_lens[b];
    int Ul  = label_lens[b];
    int tid = threadIdx.x;

    extern __shared__ float smT[];
    float*  sbS = smT;                              // SROWS * DPITCH fp32
    __half* seS = reinterpret_cast<__half*>(smT + SROWS * DPITCH);

    // Stage rows 0..SROWS-1 of this example's diag-major tiles into smem.
    {
        const float4* srcB = reinterpret_cast<const float4*>(
                                 g_blankD + (size_t)b * DROWS * DPITCH);
        const int4*   srcE = reinterpret_cast<const int4*>(
                                 g_emitD  + (size_t)b * DROWS * DPITCH);
        float4* dstB = reinterpret_cast<float4*>(sbS);
        int4*   dstE = reinterpret_cast<int4*>(seS);
        const int NB = SROWS * DSTR;                // 7852 float4
        const int NE = SROWS * DPITCH * 2 / 16;     // 3926 int4
        for (int i = tid; i < NB; i += 128) dstB[i] = srcB[i];
        for (int i = tid; i < NE; i += 128) dstE[i] = srcE[i];
    }
    __syncthreads();
    if (tid >= 32) return;

    int l = tid;
    const unsigned F = 0xffffffffu;

    const float4* bdp = reinterpret_cast<const float4*>(sbS) + l;
    const uint2*  edp = reinterpret_cast<const uint2*>(seS) + l;

    int  dmax = (Tl - 1) + Ul;                 // last diagonal (>= 149)
    int  kf   = Ul & 3;
    bool amI  = (l == (Ul >> 2));

    float a0 = (l == 0) ? 0.0f : NEG_INF;      // alpha[0][4l+k], log2 domain
    float a1 = NEG_INF, a2 = NEG_INF, a3 = NEG_INF;
    float res = NEG_INF;

    // Prime the 4-deep pipeline: stages hold (blank row d-1, emit row d).
    float4 B0 = bdp[0 * DSTR], B1 = bdp[1 * DSTR],
           B2 = bdp[2 * DSTR], B3 = bdp[3 * DSTR];
    uint2  E0 = edp[1 * DSTR], E1 = edp[2 * DSTR],
           E2 = edp[3 * DSTR], E3 = edp[4 * DSTR];

#define RCL(r) (min((r), SROWS - 1))
#define STEP(Bv, Eu, dd)                                                      \
    do {                                                                      \
        float2 e01 = __half22float2(*reinterpret_cast<const __half2*>(&Eu.x));\
        float2 e23 = __half22float2(*reinterpret_cast<const __half2*>(&Eu.y));\
        float sh = __shfl_up_sync(F, a3, 1);                                  \
        if (l == 0) sh = NEG_INF;                                             \
        float n0 = la2(a0 + Bv.x, sh + e01.x);                                \
        float n1 = la2(a1 + Bv.y, a0 + e01.y);                                \
        float n2 = la2(a2 + Bv.z, a1 + e23.x);                                \
        float n3 = la2(a3 + Bv.w, a2 + e23.y);                                \
        a0 = n0; a1 = n1; a2 = n2; a3 = n3;                                   \
        if ((dd) == dmax && amI)                                              \
            res = (kf == 0) ? a0 : (kf == 1) ? a1 : (kf == 2) ? a2 : a3;      \
    } while (0)

    int dlim = ((dmax + 3) >> 2) << 2;         // <= 300
    for (int d0 = 1; d0 <= dlim; d0 += 4) {
        STEP(B0, E0, d0);
        B0 = bdp[RCL(d0 + 3) * DSTR];  E0 = edp[RCL(d0 + 4) * DSTR];
        STEP(B1, E1, d0 + 1);
        B1 = bdp[RCL(d0 + 4) * DSTR];  E1 = edp[RCL(d0 + 5) * DSTR];
        STEP(B2, E2, d0 + 2);
        B2 = bdp[RCL(d0 + 5) * DSTR];  E2 = edp[RCL(d0 + 6) * DSTR];
        STEP(B3, E3, d0 + 3);
        B3 = bdp[RCL(d0 + 6) * DSTR];  E3 = edp[RCL(d0 + 7) * DSTR];
    }
#undef STEP
#undef RCL

    // Terminal: loss_b = -(alpha(Tl-1,Ul) + blank(Tl-1,Ul)) * ln2 / Ul.
    if (amI) {
        float bl = sbS[dmax * DPITCH + Ul];
        g_perb[b] = -((res + bl) * LN2) / (float)Ul;
        __threadfence();
        unsigned done = atomicAdd(&g_done, 1u);
        if (done == BB - 1) {                  // last example: fold the mean
            __threadfence();
            float s = 0.0f;
            #pragma unroll
            for (int i = 0; i < BB; ++i) s += __ldcg(&g_perb[i]);
            out[0] = s / (float)BB;
            g_done = 0;                        // reset for next graph replay
        }
    }
}

extern "C" void kernel_launch(void* const* d_in, const int* in_sizes, int n_in,
                              void* d_out, int out_size)
{
    const float* acts       = (const float*)d_in[0];
    const int*   labels     = (const int*)  d_in[1];
    const int*   act_lens   = (const int*)  d_in[2];
    const int*   label_lens = (const int*)  d_in[3];
    float*       out        = (float*)d_out;

    const int P     = BB * TT * UP1;          // lattice nodes
    const int pairs = P / 2;                  // two nodes per warp
    int blocks = (pairs + 7) / 8;             // 8 warps per 256-thread block
    rnnt_softmax_kernel<<<blocks, 256>>>(acts, labels, act_lens, label_lens);

    cudaFuncSetAttribute(rnnt_dp_kernel,
                         cudaFuncAttributeMaxDynamicSharedMemorySize, SMEM_BYTES);
    rnnt_dp_kernel<<<BB, 128, SMEM_BYTES>>>(act_lens, label_lens, out);
}

// round 17
// speedup vs baseline: 1.2107x; 1.0056x over previous
#include <cuda_runtime.h>
#include <cuda_bf16.h>
#include <cuda_fp16.h>

// Problem constants (fixed by the dataset):
//   acts: (B, T, U+1, V) fp32, labels: (B, U) int32, act_lens/label_lens: (B,) int32
#define BB  16
#define TT  200
#define UU  100
#define VV  256
#define UP1 101          // U + 1
#define NEG_INF (-1e30f)
#define LOG2E 1.4426950408889634f
#define LN2   0.6931471805599453f

// Diagonal-major operand tensors (log2 domain), written by the softmax kernel:
//   BD[b][d][u] (fp32) = blank[t][u] * LOG2E at d = t+u
//   ED[b][d][u] (fp16) = emit [t][u-1] * LOG2E at d = t+u   (col 0 unused)
#define DROWS  312       // global rows (padded)
#define DPITCH 104
#define DSTR   26        // row stride in float4 / uint2 units (104/4)
#define SROWS  302       // rows staged to smem (dmax <= 299; prefetch clamped)
#define SMEM_BYTES (SROWS * DPITCH * 4 + SROWS * DPITCH * 2)   // 188,448 B

// Scratch (no cudaMalloc allowed). Unwritten cells hold stale/garbage data;
// they can never influence valid lattice cells (deps flow up in u, fwd in t)
// and all arithmetic on them stays finite (no inf/NaN).
__device__ float    g_blankD[BB * DROWS * DPITCH];   // 2.08 MB
__device__ __half   g_emitD [BB * DROWS * DPITCH];   // 1.04 MB
__device__ float    g_perb  [BB];                    // per-example nll / label_len
__device__ unsigned g_done = 0;                      // block-completion counter

// ---------------------------------------------------------------------------
// Kernel 1: fused log-softmax gather, TWO (b,t,u) nodes per warp (MLP=4).
// Skips nodes outside the live lattice region. Stores DIAGONAL-MAJOR in the
// log2 domain (the scatter is free: lane-0 stores were already scattered).
// ---------------------------------------------------------------------------
__global__ __launch_bounds__(256) void rnnt_softmax_kernel(
    const float* __restrict__ acts,
    const int*   __restrict__ labels,
    const int*   __restrict__ act_lens,
    const int*   __restrict__ label_lens)
{
    const int P = BB * TT * UP1;                       // 323200 (even)
    int w    = blockIdx.x * 8 + (threadIdx.x >> 5);    // warp id
    int lane = threadIdx.x & 31;
    int n0   = w * 2;
    if (n0 >= P) return;
    int n1 = n0 + 1;

    int u0 = n0 % UP1, bt0 = n0 / UP1, t0 = bt0 % TT, b0i = bt0 / TT;
    int u1 = n1 % UP1, bt1 = n1 / UP1, t1 = bt1 % TT, b1i = bt1 / TT;

    bool L0 = (t0 < __ldg(act_lens + b0i)) && (u0 <= __ldg(label_lens + b0i));
    bool L1 = (t1 < __ldg(act_lens + b1i)) && (u1 <= __ldg(label_lens + b1i));
    if (!L0 && !L1) return;

    const float4* p0 = reinterpret_cast<const float4*>(acts) + (size_t)n0 * (VV / 4);
    const float4* p1 = p0 + (VV / 4);

    float4 a0 = {0,0,0,0}, c0 = {0,0,0,0}, a1 = {0,0,0,0}, c1 = {0,0,0,0};
    if (L0) { a0 = p0[lane]; c0 = p0[lane + 32]; }
    if (L1) { a1 = p1[lane]; c1 = p1[lane + 32]; }

    float m0 = fmaxf(fmaxf(fmaxf(a0.x, a0.y), fmaxf(a0.z, a0.w)),
                     fmaxf(fmaxf(c0.x, c0.y), fmaxf(c0.z, c0.w)));
    float m1 = fmaxf(fmaxf(fmaxf(a1.x, a1.y), fmaxf(a1.z, a1.w)),
                     fmaxf(fmaxf(c1.x, c1.y), fmaxf(c1.z, c1.w)));
    #pragma unroll
    for (int o = 16; o; o >>= 1) {
        m0 = fmaxf(m0, __shfl_xor_sync(0xffffffffu, m0, o));
        m1 = fmaxf(m1, __shfl_xor_sync(0xffffffffu, m1, o));
    }

    float s0 = __expf(a0.x - m0) + __expf(a0.y - m0) + __expf(a0.z - m0) + __expf(a0.w - m0)
             + __expf(c0.x - m0) + __expf(c0.y - m0) + __expf(c0.z - m0) + __expf(c0.w - m0);
    float s1 = __expf(a1.x - m1) + __expf(a1.y - m1) + __expf(a1.z - m1) + __expf(a1.w - m1)
             + __expf(c1.x - m1) + __expf(c1.y - m1) + __expf(c1.z - m1) + __expf(c1.w - m1);
    #pragma unroll
    for (int o = 16; o; o >>= 1) {
        s0 += __shfl_xor_sync(0xffffffffu, s0, o);
        s1 += __shfl_xor_sync(0xffffffffu, s1, o);
    }

    if (lane == 0) {
        if (L0) {
            float logZ = m0 + __logf(s0);
            size_t base = (size_t)b0i * DROWS * DPITCH;
            g_blankD[base + (size_t)(t0 + u0) * DPITCH + u0] = (a0.x - logZ) * LOG2E;
            if (u0 < UU) {
                int lbl  = labels[b0i * UU + u0];
                float lv = __ldg(acts + (size_t)n0 * VV + lbl);
                g_emitD[base + (size_t)(t0 + u0 + 1) * DPITCH + (u0 + 1)] =
                    __float2half((lv - logZ) * LOG2E);
            }
        }
        if (L1) {
            float logZ = m1 + __logf(s1);
            size_t base = (size_t)b1i * DROWS * DPITCH;
            g_blankD[base + (size_t)(t1 + u1) * DPITCH + u1] = (a1.x - logZ) * LOG2E;
            if (u1 < UU) {
                int lbl  = labels[b1i * UU + u1];
                float lv = __ldg(acts + (size_t)n1 * VV + lbl);
                g_emitD[base + (size_t)(t1 + u1 + 1) * DPITCH + (u1 + 1)] =
                    __float2half((lv - logZ) * LOG2E);
            }
        }
    }
}

// ---------------------------------------------------------------------------
// Kernel 2: per-example forward DP, ONE warp computing, lane l owns the
// contiguous u-block {4l..4l+3}. Operands from SMEM (diag-major, conflict-
// free, prefetched 4 stages ahead). The 4 cells per step are computed in
// PHASE-INTERLEAVED form (all FADDs, all FMNMX, all EX2, all LG2) so their
// independent dependency chains overlap instead of serializing; the MUFU
// latencies pipeline (rt=8). No barriers in the loop.
// Mean-reduction fused via completion counter.
// ---------------------------------------------------------------------------
__global__ __launch_bounds__(128) void rnnt_dp_kernel(
    const int* __restrict__ act_lens,
    const int* __restrict__ label_lens,
    float*     __restrict__ out)
{
    int b   = blockIdx.x;
    int Tl  = act_lens[b];
    int Ul  = label_lens[b];
    int tid = threadIdx.x;

    extern __shared__ float smT[];
    float*  sbS = smT;                              // SROWS * DPITCH fp32
    __half* seS = reinterpret_cast<__half*>(smT + SROWS * DPITCH);

    // Stage rows 0..SROWS-1 of this example's diag-major tiles into smem.
    {
        const float4* srcB = reinterpret_cast<const float4*>(
                                 g_blankD + (size_t)b * DROWS * DPITCH);
        const int4*   srcE = reinterpret_cast<const int4*>(
                                 g_emitD  + (size_t)b * DROWS * DPITCH);
        float4* dstB = reinterpret_cast<float4*>(sbS);
        int4*   dstE = reinterpret_cast<int4*>(seS);
        const int NB = SROWS * DSTR;                // 7852 float4
        const int NE = SROWS * DPITCH * 2 / 16;     // 3926 int4
        for (int i = tid; i < NB; i += 128) dstB[i] = srcB[i];
        for (int i = tid; i < NE; i += 128) dstE[i] = srcE[i];
    }
    __syncthreads();
    if (tid >= 32) return;

    int l = tid;
    const unsigned F = 0xffffffffu;

    const float4* bdp = reinterpret_cast<const float4*>(sbS) + l;
    const uint2*  edp = reinterpret_cast<const uint2*>(seS) + l;

    int  dmax = (Tl - 1) + Ul;                 // last diagonal (>= 149)
    int  kf   = Ul & 3;
    bool amI  = (l == (Ul >> 2));

    // alpha[0][4l+k], log2 domain; kept as an unrolled array for phase code.
    float a[4];
    a[0] = (l == 0) ? 0.0f : NEG_INF;
    a[1] = NEG_INF; a[2] = NEG_INF; a[3] = NEG_INF;
    float res = NEG_INF;

    // Prime the 4-deep pipeline: stages hold (blank row d-1, emit row d).
    float4 B0 = bdp[0 * DSTR], B1 = bdp[1 * DSTR],
           B2 = bdp[2 * DSTR], B3 = bdp[3 * DSTR];
    uint2  E0 = edp[1 * DSTR], E1 = edp[2 * DSTR],
           E2 = edp[3 * DSTR], E3 = edp[4 * DSTR];

#define RCL(r) (min((r), SROWS - 1))
    // Phase-interleaved step: expose the 4 cells' chains to the scheduler.
#define STEP(Bv, Eu, dd)                                                      \
    do {                                                                      \
        float2 e01 = __half22float2(*reinterpret_cast<const __half2*>(&Eu.x));\
        float2 e23 = __half22float2(*reinterpret_cast<const __half2*>(&Eu.y));\
        float sh = __shfl_up_sync(F, a[3], 1);                                \
        if (l == 0) sh = NEG_INF;                                             \
        float fb[4], fl[4], mx[4], dn[4], ex[4];                              \
        fb[0] = a[0] + Bv.x;  fb[1] = a[1] + Bv.y;                            \
        fb[2] = a[2] + Bv.z;  fb[3] = a[3] + Bv.w;                            \
        fl[0] = sh   + e01.x; fl[1] = a[0] + e01.y;                           \
        fl[2] = a[1] + e23.x; fl[3] = a[2] + e23.y;                           \
        _Pragma("unroll")                                                     \
        for (int k = 0; k < 4; ++k) mx[k] = fmaxf(fb[k], fl[k]);              \
        _Pragma("unroll")                                                     \
        for (int k = 0; k < 4; ++k) dn[k] = fminf(fb[k], fl[k]) - mx[k];      \
        _Pragma("unroll")                                                     \
        for (int k = 0; k < 4; ++k) ex[k] = exp2f(dn[k]);                     \
        _Pragma("unroll")                                                     \
        for (int k = 0; k < 4; ++k) ex[k] = 1.0f + ex[k];                     \
        _Pragma("unroll")                                                     \
        for (int k = 0; k < 4; ++k) ex[k] = __log2f(ex[k]);                   \
        _Pragma("unroll")                                                     \
        for (int k = 0; k < 4; ++k) a[k] = mx[k] + ex[k];                     \
        if ((dd) == dmax && amI) res = a[kf];                                 \
    } while (0)

    int dlim = ((dmax + 3) >> 2) << 2;         // <= 300
    for (int d0 = 1; d0 <= dlim; d0 += 4) {
        STEP(B0, E0, d0);
        B0 = bdp[RCL(d0 + 3) * DSTR];  E0 = edp[RCL(d0 + 4) * DSTR];
        STEP(B1, E1, d0 + 1);
        B1 = bdp[RCL(d0 + 4) * DSTR];  E1 = edp[RCL(d0 + 5) * DSTR];
        STEP(B2, E2, d0 + 2);
        B2 = bdp[RCL(d0 + 5) * DSTR];  E2 = edp[RCL(d0 + 6) * DSTR];
        STEP(B3, E3, d0 + 3);
        B3 = bdp[RCL(d0 + 6) * DSTR];  E3 = edp[RCL(d0 + 7) * DSTR];
    }
#undef STEP
#undef RCL

    // Terminal: loss_b = -(alpha(Tl-1,Ul) + blank(Tl-1,Ul)) * ln2 / Ul.
    if (amI) {
        float bl = sbS[dmax * DPITCH + Ul];
        g_perb[b] = -((res + bl) * LN2) / (float)Ul;
        __threadfence();
        unsigned done = atomicAdd(&g_done, 1u);
        if (done == BB - 1) {                  // last example: fold the mean
            __threadfence();
            float s = 0.0f;
            #pragma unroll
            for (int i = 0; i < BB; ++i) s += __ldcg(&g_perb[i]);
            out[0] = s / (float)BB;
            g_done = 0;                        // reset for next graph replay
        }
    }
}

extern "C" void kernel_launch(void* const* d_in, const int* in_sizes, int n_in,
                              void* d_out, int out_size)
{
    const float* acts       = (const float*)d_in[0];
    const int*   labels     = (const int*)  d_in[1];
    const int*   act_lens   = (const int*)  d_in[2];
    const int*   label_lens = (const int*)  d_in[3];
    float*       out        = (float*)d_out;

    const int P     = BB * TT * UP1;          // lattice nodes
    const int pairs = P / 2;                  // two nodes per warp
    int blocks = (pairs + 7) / 8;             // 8 warps per 256-thread block
    rnnt_softmax_kernel<<<blocks, 256>>>(acts, labels, act_lens, label_lens);

    cudaFuncSetAttribute(rnnt_dp_kernel,
                         cudaFuncAttributeMaxDynamicSharedMemorySize, SMEM_BYTES);
    rnnt_dp_kernel<<<BB, 128, SMEM_BYTES>>>(act_lens, label_lens, out);
}